// round 15
// baseline (speedup 1.0000x reference)
#include <cuda_runtime.h>
#include <cuda_fp16.h>
#include <math.h>
#include <float.h>
#include <stdint.h>

#define N       16384
#define DIN     13
#define KNN     8
#define NBIN    1024
#define QCTA    128              // sorted queries per CTA (8 warps x m16)
#define CHUNK   128              // j per chunk
#define NCHUNK  (N / CHUNK)      // 128
#define NTILE   (CHUNK / 8)      // 16 tiles per chunk
#define NTILES  (N / 8)          // 2048 global tiles
#define NLIST   4                // 4 t4-slices
#define EPSA    1e-3f            // abs margin on d2 threshold (MMA approx)
#define SLACK   0.02f            // key slack for chunk bounds (> bin width)

typedef unsigned long long ull;

// ---- scratch (no allocs allowed) ----
__device__ float  g_x[N * 16];            // embedded points (original order)
__device__ float  g_sq[N];
__device__ float  g_key[N];
__device__ int    g_hist[NBIN];
__device__ int    g_off[NBIN];
__device__ float  g_pkey[N];              // sorted keys
__device__ float  g_psq[N];               // sorted sq
__device__ int    g_pidx[N];              // sorted pos -> original index
__device__ __half g_ah[N * 16];           // sorted fp16 hi of -2x
__device__ __half g_am[N * 16];           // sorted fp16 mid of -2x
__device__ uint4  g_bf[NCHUNK * NTILE * 32]; // sorted B fragments
__device__ float  g_clo[NCHUNK], g_chi[NCHUNK];
__device__ float  g_tlo[NTILES], g_thi[NTILES];
__device__ int    g_idx[N * KNN];         // final knn (original indices)

__device__ __forceinline__ float silu_f(float v) { return v / (1.0f + expf(-v)); }
__device__ __forceinline__ float silu_fast(float v) { return __fdividef(v, 1.0f + __expf(-v)); }
__device__ __forceinline__ int keybin(float k) {
    int b = (int)((k + 5.0f) * (NBIN / 10.0f));
    return b < 0 ? 0 : (b > NBIN - 1 ? NBIN - 1 : b);
}
__device__ __forceinline__ uint32_t smem_u32(const void* p) {
    uint32_t a;
    asm("{ .reg .u64 t; cvta.to.shared.u64 t, %1; cvt.u32.u64 %0, t; }"
        : "=r"(a) : "l"(p));
    return a;
}
__device__ __forceinline__ void cp_async16(uint32_t saddr, const void* g) {
    asm volatile("cp.async.cg.shared.global [%0], [%1], 16;" :: "r"(saddr), "l"(g));
}
#define CP_COMMIT() asm volatile("cp.async.commit_group;" ::: "memory")
#define CP_WAIT0()  asm volatile("cp.async.wait_group 0;" ::: "memory")

// sortable uint from float (ascending uint == ascending float, any sign)
__device__ __forceinline__ uint32_t fkey(float f) {
    uint32_t u = __float_as_uint(f);
    return u ^ ((u >> 31) ? 0xFFFFFFFFu : 0x80000000u);
}

// m16n8k16 fp16 mma, fp32 accumulate (PTX sm_80+, valid under compute_103)
__device__ __forceinline__ void mma_f16(float& c0, float& c1, float& c2, float& c3,
                                        uint32_t a0, uint32_t a1, uint32_t a2, uint32_t a3,
                                        uint32_t b0, uint32_t b1) {
    asm volatile(
        "mma.sync.aligned.m16n8k16.row.col.f32.f16.f16.f32 "
        "{%0,%1,%2,%3}, {%4,%5,%6,%7}, {%8,%9}, {%0,%1,%2,%3};"
        : "+f"(c0), "+f"(c1), "+f"(c2), "+f"(c3)
        : "r"(a0), "r"(a1), "r"(a2), "r"(a3), "r"(b0), "r"(b1));
}

__device__ __forceinline__ void ins8(float* td, int* ti, float d, int j) {
    if (d < td[KNN - 1]) {
        td[KNN - 1] = d; ti[KNN - 1] = j;
        #pragma unroll
        for (int s = KNN - 1; s >= 1; --s) {
            if (td[s] < td[s - 1] || (td[s] == td[s - 1] && ti[s] < ti[s - 1])) {
                float tf = td[s]; td[s] = td[s-1]; td[s-1] = tf;
                int   tn = ti[s]; ti[s] = ti[s-1]; ti[s-1] = tn;
            }
        }
    }
}

// ============================================================
// Kernel 0: zero histogram
// ============================================================
__global__ void zeroh_kernel() { g_hist[threadIdx.x] = 0; }

// ============================================================
// Kernel 1: per-point MLP -> x, sq, key + histogram (fused)
// ============================================================
__global__ void mlp_kernel(const float* __restrict__ xp,
                           const float* __restrict__ W1, const float* __restrict__ b1,
                           const float* __restrict__ W2, const float* __restrict__ b2,
                           const float* __restrict__ W3, const float* __restrict__ b3)
{
    __shared__ float sW1[DIN * 8], sb1[8];
    __shared__ float sW2[8 * 16],  sb2[16];
    __shared__ float sW3[16 * 15], sb3[15];

    int t = threadIdx.x;
    for (int i = t; i < DIN * 8; i += blockDim.x) sW1[i] = W1[i];
    for (int i = t; i < 8;       i += blockDim.x) sb1[i] = b1[i];
    for (int i = t; i < 8 * 16;  i += blockDim.x) sW2[i] = W2[i];
    for (int i = t; i < 16;      i += blockDim.x) sb2[i] = b2[i];
    for (int i = t; i < 16 * 15; i += blockDim.x) sW3[i] = W3[i];
    for (int i = t; i < 15;      i += blockDim.x) sb3[i] = b3[i];
    __syncthreads();

    int i = blockIdx.x * blockDim.x + t;
    if (i >= N) return;

    float in[DIN];
    #pragma unroll
    for (int d = 0; d < DIN; ++d) in[d] = xp[i * DIN + d];

    float h1[8];
    #pragma unroll
    for (int h = 0; h < 8; ++h) {
        float a = sb1[h];
        #pragma unroll
        for (int d = 0; d < DIN; ++d) a = fmaf(in[d], sW1[d * 8 + h], a);
        h1[h] = silu_f(a);
    }
    float h2[16];
    #pragma unroll
    for (int h = 0; h < 16; ++h) {
        float a = sb2[h];
        #pragma unroll
        for (int d = 0; d < 8; ++d) a = fmaf(h1[d], sW2[d * 16 + h], a);
        h2[h] = silu_f(a);
    }
    float xr[16];
    #pragma unroll
    for (int h = 0; h < 15; ++h) {
        float a = sb3[h];
        #pragma unroll
        for (int d = 0; d < 16; ++d) a = fmaf(h2[d], sW3[d * 15 + h], a);
        xr[h] = a;
    }
    xr[15] = in[DIN - 1];

    float s = 0.0f;
    #pragma unroll
    for (int k = 0; k < 16; ++k) s = fmaf(xr[k], xr[k], s);

    #pragma unroll
    for (int k = 0; k < 16; ++k) g_x[i * 16 + k] = xr[k];
    g_sq[i]  = s;
    g_key[i] = xr[15];
    atomicAdd(&g_hist[keybin(xr[15])], 1);
}

// ============================================================
// Kernel 2: single-warp exclusive scan of 1024 bins
// ============================================================
__global__ void scan_kernel() {
    int lane = threadIdx.x;     // 32 threads
    int base = lane * 32;
    int vals[32];
    int sum = 0;
    #pragma unroll
    for (int i = 0; i < 32; ++i) { vals[i] = g_hist[base + i]; sum += vals[i]; }
    int inc = sum;
    #pragma unroll
    for (int d = 1; d < 32; d <<= 1) {
        int o = __shfl_up_sync(0xffffffffu, inc, d);
        if (lane >= d) inc += o;
    }
    int run = inc - sum;   // exclusive offset of this lane's block
    #pragma unroll
    for (int i = 0; i < 32; ++i) { g_off[base + i] = run; run += vals[i]; }
}

// ============================================================
// Kernel 3: scatter (2 independent points/thread for ILP)
// ============================================================
__device__ __forceinline__ void scatter_one(int i) {
    float key = g_key[i];
    int b = keybin(key);
    int pos = atomicAdd(&g_off[b], 1);

    float xr[16];
    #pragma unroll
    for (int d = 0; d < 16; ++d) xr[d] = g_x[i * 16 + d];

    g_pkey[pos] = key;
    g_psq[pos]  = g_sq[i];
    g_pidx[pos] = i;

    __half ahv[16], amv[16];
    #pragma unroll
    for (int k = 0; k < 16; ++k) {
        float a = -2.0f * xr[k];
        __half ah = __float2half_rn(a);
        ahv[k] = ah;
        amv[k] = __float2half_rn(a - __half2float(ah));
    }
    {
        const uint4* av = (const uint4*)ahv;
        const uint4* mv = (const uint4*)amv;
        uint4* dsta = (uint4*)&g_ah[(size_t)pos * 16];
        uint4* dstm = (uint4*)&g_am[(size_t)pos * 16];
        dsta[0] = av[0]; dsta[1] = av[1];
        dstm[0] = mv[0]; dstm[1] = mv[1];
    }

    int T = pos >> 3, r = pos & 7;
    #pragma unroll
    for (int c = 0; c < 4; ++c) {
        int cc = 2 * c;
        float v0 = xr[cc], v1 = xr[cc + 1], v2 = xr[cc + 8], v3 = xr[cc + 9];
        __half h0 = __float2half_rn(v0), h1 = __float2half_rn(v1);
        __half h2 = __float2half_rn(v2), h3 = __float2half_rn(v3);
        __half m0 = __float2half_rn(v0 - __half2float(h0));
        __half m1 = __float2half_rn(v1 - __half2float(h1));
        __half m2 = __float2half_rn(v2 - __half2float(h2));
        __half m3 = __float2half_rn(v3 - __half2float(h3));
        uint4 f; __half2 p;
        p = __halves2half2(h0, h1); f.x = *(uint32_t*)&p;
        p = __halves2half2(h2, h3); f.y = *(uint32_t*)&p;
        p = __halves2half2(m0, m1); f.z = *(uint32_t*)&p;
        p = __halves2half2(m2, m3); f.w = *(uint32_t*)&p;
        g_bf[(size_t)T * 32 + r * 4 + c] = f;
    }
}

__global__ void scatter_kernel() {
    int i = blockIdx.x * blockDim.x + threadIdx.x;
    scatter_one(i);
    scatter_one(i + N / 2);
}

// ============================================================
// Kernel 3b: tile + chunk key bounds from sorted keys (one block)
// ============================================================
__global__ void bounds_kernel() {
    int t = threadIdx.x;   // 1024
    #pragma unroll
    for (int u = t; u < NTILES; u += 1024) {
        const float* k = g_pkey + (size_t)u * 8;
        float lo = k[0], hi = k[0];
        #pragma unroll
        for (int r = 1; r < 8; ++r) { lo = fminf(lo, k[r]); hi = fmaxf(hi, k[r]); }
        g_tlo[u] = lo; g_thi[u] = hi;
    }
    __syncthreads();
    if (t < NCHUNK) {
        float lo = FLT_MAX, hi = -FLT_MAX;
        #pragma unroll
        for (int r = 0; r < NTILE; ++r) {
            lo = fminf(lo, g_tlo[t * NTILE + r]);
            hi = fmaxf(hi, g_thi[t * NTILE + r]);
        }
        g_clo[t] = lo; g_chi[t] = hi;
    }
}

// ============================================================
// Kernel 4: zigzag-pruned KNN (128 q/CTA) + in-CTA merge
// ============================================================
__global__ void __launch_bounds__(256) knn_zig_kernel()
{
    __shared__ uint4 sBf[2][NTILE * 32];   // 2 x 8KB
    __shared__ float ssq[2][CHUNK];
    __shared__ int   sjd[2][CHUNK];
    __shared__ ull   smerge[QCTA * NLIST * KNN];   // 32KB

    const int t    = threadIdx.x;
    const int lane = t & 31;
    const int w    = t >> 5;            // q-group 0..7
    const int gid  = lane >> 2;
    const int t4   = lane & 3;
    const int b    = blockIdx.x;
    const int p0   = b * QCTA + w * 16 + gid;   // sorted query rows
    const int p1   = p0 + 8;

    uint32_t ah[4], am[4];
    {
        const __half* A0h = g_ah + (size_t)p0 * 16;
        const __half* A1h = g_ah + (size_t)p1 * 16;
        const __half* A0m = g_am + (size_t)p0 * 16;
        const __half* A1m = g_am + (size_t)p1 * 16;
        ah[0] = *(const uint32_t*)&A0h[2 * t4];
        ah[1] = *(const uint32_t*)&A1h[2 * t4];
        ah[2] = *(const uint32_t*)&A0h[2 * t4 + 8];
        ah[3] = *(const uint32_t*)&A1h[2 * t4 + 8];
        am[0] = *(const uint32_t*)&A0m[2 * t4];
        am[1] = *(const uint32_t*)&A1m[2 * t4];
        am[2] = *(const uint32_t*)&A0m[2 * t4 + 8];
        am[3] = *(const uint32_t*)&A1m[2 * t4 + 8];
    }
    const float qk0 = g_pkey[p0], qk1 = g_pkey[p1];
    const float sq0 = g_psq[p0],  sq1 = g_psq[p1];

    float td0[KNN], td1[KNN];
    int   ti0[KNN], ti1[KNN];
    #pragma unroll
    for (int k = 0; k < KNN; ++k) {
        td0[k] = FLT_MAX; ti0[k] = 0x7fffffff;
        td1[k] = FLT_MAX; ti1[k] = 0x7fffffff;
    }

    uint32_t sB_addr[2], sq_addr[2], sj_addr[2];
    #pragma unroll
    for (int u = 0; u < 2; ++u) {
        sB_addr[u] = smem_u32(&sBf[u][0]);
        sq_addr[u] = smem_u32(&ssq[u][0]);
        sj_addr[u] = smem_u32(&sjd[u][0]);
    }

    auto stage = [&](int bf, int c) {
        const uint4* src = g_bf + (size_t)c * (NTILE * 32);
        cp_async16(sB_addr[bf] + (uint32_t)t * 16, src + t);
        cp_async16(sB_addr[bf] + (uint32_t)(t + 256) * 16, src + t + 256);
        if (t < 32) {
            cp_async16(sq_addr[bf] + (uint32_t)t * 16, (const float4*)(g_psq + c * CHUNK) + t);
            cp_async16(sj_addr[bf] + (uint32_t)t * 16, (const int4*)(g_pidx + c * CHUNK) + t);
        }
        CP_COMMIT();
    };

    const int h0 = b;                    // home chunk (QCTA == CHUNK)
    int nxtR = h0 + 1, nxtL = h0 - 1;
    int aliveR = 1, aliveL = 1, tog = 0;
    int cur = h0, bufA = 0;

    stage(0, h0);
    CP_WAIT0();
    __syncthreads();

    while (cur >= 0) {
        int pred = -1;
        {
            int aR = aliveR && (nxtR < NCHUNK);
            int aL = aliveL && (nxtL >= 0);
            if (aR && aL) pred = (tog == 0) ? nxtR : nxtL;
            else if (aR)  pred = nxtR;
            else if (aL)  pred = nxtL;
        }
        if (pred >= 0) stage(bufA ^ 1, pred);

        // ---- all 16 tiles of this chunk (per-warp tile skip) ----
        #pragma unroll
        for (int tl = 0; tl < NTILE; ++tl) {
            const int gt = cur * NTILE + tl;

            float tlo = g_tlo[gt], thi = g_thi[gt];
            float gp0 = fmaxf(fmaxf(tlo - qk0, qk0 - thi), 0.0f);
            float gp1 = fmaxf(fmaxf(tlo - qk1, qk1 - thi), 0.0f);
            int nd = (gp0 * gp0 <= td0[KNN - 1] + sq0 + EPSA) ||
                     (gp1 * gp1 <= td1[KNN - 1] + sq1 + EPSA);
            if (!__any_sync(0xffffffffu, nd)) continue;

            uint4 f = sBf[bufA][tl * 32 + lane];
            const int jl = tl * 8 + 2 * t4;
            float2 s2 = *(const float2*)&ssq[bufA][jl];
            float c0 = s2.x, c1 = s2.y, c2 = s2.x, c3 = s2.y;
            mma_f16(c0, c1, c2, c3, ah[0], ah[1], ah[2], ah[3], f.x, f.y);
            mma_f16(c0, c1, c2, c3, ah[0], ah[1], ah[2], ah[3], f.z, f.w);
            mma_f16(c0, c1, c2, c3, am[0], am[1], am[2], am[3], f.x, f.y);
            if (fminf(c0, c1) < td0[KNN - 1]) {
                ins8(td0, ti0, c0, sjd[bufA][jl]); ins8(td0, ti0, c1, sjd[bufA][jl + 1]);
            }
            if (fminf(c2, c3) < td1[KNN - 1]) {
                ins8(td1, ti1, c2, sjd[bufA][jl]); ins8(td1, ti1, c3, sjd[bufA][jl + 1]);
            }
        }

        cur = -1;
        while (aliveR || aliveL) {
            int dir;
            if (aliveR && aliveL) { dir = tog; tog ^= 1; }
            else dir = aliveR ? 0 : 1;
            int c = (dir == 0) ? nxtR : nxtL;
            if (c < 0 || c >= NCHUNK) {
                if (dir == 0) aliveR = 0; else aliveL = 0;
                continue;
            }
            float bnd = (dir == 0) ? g_clo[c] : g_chi[c];
            float gp0 = (dir == 0) ? bnd - qk0 : qk0 - bnd;
            float gp1 = (dir == 0) ? bnd - qk1 : qk1 - bnd;
            gp0 = fmaxf(gp0 - SLACK, 0.0f);
            gp1 = fmaxf(gp1 - SLACK, 0.0f);
            float th0 = td0[KNN - 1] + sq0 + EPSA;
            float th1 = td1[KNN - 1] + sq1 + EPSA;
            int nd = (gp0 * gp0 <= th0) || (gp1 * gp1 <= th1);
            if (__syncthreads_or(nd)) {
                cur = c;
                if (dir == 0) nxtR++; else nxtL--;
                break;
            } else {
                if (dir == 0) aliveR = 0; else aliveL = 0;
            }
        }

        if (cur >= 0) {
            CP_WAIT0();
            __syncthreads();
            if (cur != pred) {
                stage(bufA ^ 1, cur);
                CP_WAIT0();
                __syncthreads();
            }
            bufA ^= 1;
        }
    }
    CP_WAIT0();

    // ---- in-CTA merge: 128 queries x 4 lists x 8 entries ----
    {
        const int q0l = w * 16 + gid;
        const int q1l = q0l + 8;
        #pragma unroll
        for (int k = 0; k < KNN; ++k) {
            smerge[(q0l * NLIST + t4) * KNN + k] = ((ull)fkey(td0[k]) << 32) | (uint32_t)ti0[k];
            smerge[(q1l * NLIST + t4) * KNN + k] = ((ull)fkey(td1[k]) << 32) | (uint32_t)ti1[k];
        }
    }
    __syncthreads();

    // 512 (query,list) units on 256 threads: 2 passes, 4-lane shfl merge
    #pragma unroll
    for (int pass = 0; pass < 2; ++pass) {
        int u  = pass * 256 + t;
        int q  = u >> 2;          // local query 0..127
        int l  = u & 3;
        ull v[KNN];
        #pragma unroll
        for (int k = 0; k < KNN; ++k)
            v[k] = smerge[(q * NLIST + l) * KNN + k];
        int oi = g_pidx[b * QCTA + q];
        #pragma unroll
        for (int k = 0; k < KNN; ++k) {
            ull m = v[0];
            #pragma unroll
            for (int x = 1; x < KNN; ++x) m = (v[x] < m) ? v[x] : m;
            #pragma unroll
            for (int off = 1; off < 4; off <<= 1) {
                ull o = __shfl_xor_sync(0xffffffffu, m, off, 4);
                m = (o < m) ? o : m;
            }
            if (l == 0)
                g_idx[oi * KNN + k] = (int)(uint32_t)(m & 0xffffffffull);
            #pragma unroll
            for (int x = 0; x < KNN; ++x)
                if (v[x] == m) v[x] = ~0ull;
        }
    }
}

// ============================================================
// Kernel 5: fused edge messages + mean + out MLP + concat
// ============================================================
__global__ void __launch_bounds__(256)
feats_out_kernel(const float* __restrict__ xp,
                 const float* __restrict__ We,  const float* __restrict__ be,
                 const float* __restrict__ Wf1, const float* __restrict__ bf1,
                 const float* __restrict__ Wf2, const float* __restrict__ bf2,
                 float* __restrict__ out)
{
    __shared__ float sWd[16 * 16];
    __shared__ float sWb[16 * 16];
    __shared__ float sbe[16];
    __shared__ float sWf1[16 * 32], sbf1[32];
    __shared__ float sWf2[32 * 16], sbf2[16];
    __shared__ float sxi[16 * 16];
    __shared__ int   sj[16 * KNN];
    __shared__ float sxj[16 * KNN * 16];
    __shared__ float sfe[16 * 16];
    __shared__ float sf1[16 * 32];

    const int t  = threadIdx.x;
    const int i0 = blockIdx.x * 16;

    {
        float top = We[t];
        float bot = We[256 + t];
        sWd[t] = top - bot;
        sWb[t] = bot;
    }
    if (t < 16) sbe[t] = be[t];
    for (int u = t; u < 16 * 32; u += 256) sWf1[u] = Wf1[u];
    if (t < 32) sbf1[t] = bf1[t];
    for (int u = t; u < 32 * 16; u += 256) sWf2[u] = Wf2[u];
    if (t < 16) sbf2[t] = bf2[t];
    sxi[t] = g_x[i0 * 16 + t];
    if (t < 16 * KNN) sj[t] = g_idx[i0 * KNN + t];
    __syncthreads();

    {
        const float4* gx4 = (const float4*)g_x;
        float4* sxj4 = (float4*)sxj;
        #pragma unroll
        for (int u = t; u < 16 * KNN * 4; u += 256) {
            int row = u >> 2, seg = u & 3;
            sxj4[u] = gx4[sj[row] * 4 + seg];
        }
    }
    __syncthreads();

    const int p = t >> 4;
    const int h = t & 15;
    const int i = i0 + p;

    float pre = sbe[h];
    #pragma unroll
    for (int d = 0; d < 16; ++d) pre = fmaf(sxi[p * 16 + d], sWd[d * 16 + h], pre);

    float fsum = 0.0f;
    #pragma unroll
    for (int k = 0; k < KNN; ++k) {
        const float* xj = sxj + (p * KNN + k) * 16;
        float m = pre;
        #pragma unroll
        for (int d = 0; d < 16; ++d) m = fmaf(xj[d], sWb[d * 16 + h], m);
        fsum += silu_fast(m);
    }
    sfe[p * 16 + h] = fsum * 0.125f;
    __syncthreads();

    {
        float a0 = sbf1[h], a1 = sbf1[h + 16];
        #pragma unroll
        for (int d = 0; d < 16; ++d) {
            float fe = sfe[p * 16 + d];
            a0 = fmaf(fe, sWf1[d * 32 + h], a0);
            a1 = fmaf(fe, sWf1[d * 32 + h + 16], a1);
        }
        sf1[p * 32 + h]      = silu_fast(a0);
        sf1[p * 32 + h + 16] = silu_fast(a1);
    }
    __syncthreads();

    {
        float a = sbf2[h];
        #pragma unroll
        for (int d = 0; d < 32; ++d) a = fmaf(sf1[p * 32 + d], sWf2[d * 16 + h], a);
        out[i * (16 + DIN) + h] = a;
    }
    if (h < DIN)
        out[i * (16 + DIN) + 16 + h] = xp[i * DIN + h];
}

// ============================================================
extern "C" void kernel_launch(void* const* d_in, const int* in_sizes, int n_in,
                              void* d_out, int out_size)
{
    const float* xp  = (const float*)d_in[0];
    const float* W1  = (const float*)d_in[1];
    const float* b1  = (const float*)d_in[2];
    const float* W2  = (const float*)d_in[3];
    const float* b2  = (const float*)d_in[4];
    const float* W3  = (const float*)d_in[5];
    const float* b3  = (const float*)d_in[6];
    const float* We  = (const float*)d_in[7];
    const float* be  = (const float*)d_in[8];
    const float* Wf1 = (const float*)d_in[9];
    const float* bf1 = (const float*)d_in[10];
    const float* Wf2 = (const float*)d_in[11];
    const float* bf2 = (const float*)d_in[12];
    float* out = (float*)d_out;

    zeroh_kernel<<<1, NBIN>>>();
    mlp_kernel<<<N / 256, 256>>>(xp, W1, b1, W2, b2, W3, b3);
    scan_kernel<<<1, 32>>>();
    scatter_kernel<<<(N / 2) / 128, 128>>>();
    bounds_kernel<<<1, 1024>>>();
    knn_zig_kernel<<<N / QCTA, 256>>>();
    feats_out_kernel<<<N / 16, 256>>>(xp, We, be, Wf1, bf1, Wf2, bf2, out);
}

// round 16
// speedup vs baseline: 1.3930x; 1.3930x over previous
#include <cuda_runtime.h>
#include <cuda_fp16.h>
#include <math.h>
#include <float.h>
#include <stdint.h>

#define N       16384
#define DIN     13
#define KNN     8
#define NBIN    1024
#define QCTA    64               // sorted queries per CTA
#define CHUNK   128              // j per chunk
#define NCHUNK  (N / CHUNK)      // 128
#define NTILE   (CHUNK / 8)      // 16 tiles per chunk
#define NTILES  (N / 8)          // 2048 global tiles
#define NLIST   8                // 4 t4-slices x 2 tile-halves
#define EPSA    1e-3f            // abs margin on d2 threshold (MMA approx)
#define SLACK   0.02f            // key slack for chunk bounds (> bin width)

typedef unsigned long long ull;

// ---- scratch (no allocs allowed) ----
__device__ float  g_x[N * 16];            // embedded points (original order)
__device__ float  g_sq[N];
__device__ float  g_key[N];
__device__ int    g_hist[NBIN];
__device__ int    g_off[NBIN];
__device__ float  g_pkey[N];              // sorted keys
__device__ float  g_psq[N];               // sorted sq
__device__ int    g_pidx[N];              // sorted pos -> original index
__device__ __half g_ah[N * 16];           // sorted fp16 hi of -2x
__device__ __half g_am[N * 16];           // sorted fp16 mid of -2x
__device__ uint4  g_bf[NCHUNK * NTILE * 32]; // sorted B fragments
__device__ float  g_clo[NCHUNK], g_chi[NCHUNK];
__device__ float  g_tlo[NTILES], g_thi[NTILES];
__device__ int    g_idx[N * KNN];         // final knn (original indices)

__device__ __forceinline__ float silu_f(float v) { return v / (1.0f + expf(-v)); }
__device__ __forceinline__ float silu_fast(float v) { return __fdividef(v, 1.0f + __expf(-v)); }
__device__ __forceinline__ int keybin(float k) {
    int b = (int)((k + 5.0f) * (NBIN / 10.0f));
    return b < 0 ? 0 : (b > NBIN - 1 ? NBIN - 1 : b);
}
__device__ __forceinline__ uint32_t smem_u32(const void* p) {
    uint32_t a;
    asm("{ .reg .u64 t; cvta.to.shared.u64 t, %1; cvt.u32.u64 %0, t; }"
        : "=r"(a) : "l"(p));
    return a;
}
__device__ __forceinline__ void cp_async16(uint32_t saddr, const void* g) {
    asm volatile("cp.async.cg.shared.global [%0], [%1], 16;" :: "r"(saddr), "l"(g));
}
#define CP_COMMIT() asm volatile("cp.async.commit_group;" ::: "memory")
#define CP_WAIT0()  asm volatile("cp.async.wait_group 0;" ::: "memory")

// sortable uint from float (ascending uint == ascending float, any sign)
__device__ __forceinline__ uint32_t fkey(float f) {
    uint32_t u = __float_as_uint(f);
    return u ^ ((u >> 31) ? 0xFFFFFFFFu : 0x80000000u);
}

// m16n8k16 fp16 mma, fp32 accumulate (PTX sm_80+, valid under compute_103)
__device__ __forceinline__ void mma_f16(float& c0, float& c1, float& c2, float& c3,
                                        uint32_t a0, uint32_t a1, uint32_t a2, uint32_t a3,
                                        uint32_t b0, uint32_t b1) {
    asm volatile(
        "mma.sync.aligned.m16n8k16.row.col.f32.f16.f16.f32 "
        "{%0,%1,%2,%3}, {%4,%5,%6,%7}, {%8,%9}, {%0,%1,%2,%3};"
        : "+f"(c0), "+f"(c1), "+f"(c2), "+f"(c3)
        : "r"(a0), "r"(a1), "r"(a2), "r"(a3), "r"(b0), "r"(b1));
}

__device__ __forceinline__ void ins8(float* td, int* ti, float d, int j) {
    if (d < td[KNN - 1]) {
        td[KNN - 1] = d; ti[KNN - 1] = j;
        #pragma unroll
        for (int s = KNN - 1; s >= 1; --s) {
            if (td[s] < td[s - 1] || (td[s] == td[s - 1] && ti[s] < ti[s - 1])) {
                float tf = td[s]; td[s] = td[s-1]; td[s-1] = tf;
                int   tn = ti[s]; ti[s] = ti[s-1]; ti[s-1] = tn;
            }
        }
    }
}

// ============================================================
// Kernel 0: zero histogram
// ============================================================
__global__ void zeroh_kernel() { g_hist[threadIdx.x] = 0; }

// ============================================================
// Kernel 1: per-point MLP -> x, sq, key + histogram (fused)
// ============================================================
__global__ void mlp_kernel(const float* __restrict__ xp,
                           const float* __restrict__ W1, const float* __restrict__ b1,
                           const float* __restrict__ W2, const float* __restrict__ b2,
                           const float* __restrict__ W3, const float* __restrict__ b3)
{
    __shared__ float sW1[DIN * 8], sb1[8];
    __shared__ float sW2[8 * 16],  sb2[16];
    __shared__ float sW3[16 * 15], sb3[15];

    int t = threadIdx.x;
    for (int i = t; i < DIN * 8; i += blockDim.x) sW1[i] = W1[i];
    for (int i = t; i < 8;       i += blockDim.x) sb1[i] = b1[i];
    for (int i = t; i < 8 * 16;  i += blockDim.x) sW2[i] = W2[i];
    for (int i = t; i < 16;      i += blockDim.x) sb2[i] = b2[i];
    for (int i = t; i < 16 * 15; i += blockDim.x) sW3[i] = W3[i];
    for (int i = t; i < 15;      i += blockDim.x) sb3[i] = b3[i];
    __syncthreads();

    int i = blockIdx.x * blockDim.x + t;
    if (i >= N) return;

    float in[DIN];
    #pragma unroll
    for (int d = 0; d < DIN; ++d) in[d] = xp[i * DIN + d];

    float h1[8];
    #pragma unroll
    for (int h = 0; h < 8; ++h) {
        float a = sb1[h];
        #pragma unroll
        for (int d = 0; d < DIN; ++d) a = fmaf(in[d], sW1[d * 8 + h], a);
        h1[h] = silu_f(a);
    }
    float h2[16];
    #pragma unroll
    for (int h = 0; h < 16; ++h) {
        float a = sb2[h];
        #pragma unroll
        for (int d = 0; d < 8; ++d) a = fmaf(h1[d], sW2[d * 16 + h], a);
        h2[h] = silu_f(a);
    }
    float xr[16];
    #pragma unroll
    for (int h = 0; h < 15; ++h) {
        float a = sb3[h];
        #pragma unroll
        for (int d = 0; d < 16; ++d) a = fmaf(h2[d], sW3[d * 15 + h], a);
        xr[h] = a;
    }
    xr[15] = in[DIN - 1];

    float s = 0.0f;
    #pragma unroll
    for (int k = 0; k < 16; ++k) s = fmaf(xr[k], xr[k], s);

    #pragma unroll
    for (int k = 0; k < 16; ++k) g_x[i * 16 + k] = xr[k];
    g_sq[i]  = s;
    g_key[i] = xr[15];
    atomicAdd(&g_hist[keybin(xr[15])], 1);
}

// ============================================================
// Kernel 2: single-warp exclusive scan of 1024 bins
// ============================================================
__global__ void scan_kernel() {
    int lane = threadIdx.x;     // 32 threads
    int base = lane * 32;
    int vals[32];
    int sum = 0;
    #pragma unroll
    for (int i = 0; i < 32; ++i) { vals[i] = g_hist[base + i]; sum += vals[i]; }
    int inc = sum;
    #pragma unroll
    for (int d = 1; d < 32; d <<= 1) {
        int o = __shfl_up_sync(0xffffffffu, inc, d);
        if (lane >= d) inc += o;
    }
    int run = inc - sum;   // exclusive offset of this lane's block
    #pragma unroll
    for (int i = 0; i < 32; ++i) { g_off[base + i] = run; run += vals[i]; }
}

// ============================================================
// Kernel 3: scatter + sorted A splits (vectorized) + B fragments
// ============================================================
__global__ void scatter_kernel() {
    int i = blockIdx.x * blockDim.x + threadIdx.x;
    float key = g_key[i];
    int b = keybin(key);
    int pos = atomicAdd(&g_off[b], 1);

    float xr[16];
    #pragma unroll
    for (int d = 0; d < 16; ++d) xr[d] = g_x[i * 16 + d];

    g_pkey[pos] = key;
    g_psq[pos]  = g_sq[i];
    g_pidx[pos] = i;

    // fp16 splits of -2x, built in registers, stored as 2+2 uint4
    __half ahv[16], amv[16];
    #pragma unroll
    for (int k = 0; k < 16; ++k) {
        float a = -2.0f * xr[k];
        __half ah = __float2half_rn(a);
        ahv[k] = ah;
        amv[k] = __float2half_rn(a - __half2float(ah));
    }
    {
        const uint4* av = (const uint4*)ahv;
        const uint4* mv = (const uint4*)amv;
        uint4* dsta = (uint4*)&g_ah[(size_t)pos * 16];
        uint4* dstm = (uint4*)&g_am[(size_t)pos * 16];
        dsta[0] = av[0]; dsta[1] = av[1];
        dstm[0] = mv[0]; dstm[1] = mv[1];
    }

    int T = pos >> 3, r = pos & 7;
    #pragma unroll
    for (int c = 0; c < 4; ++c) {
        int cc = 2 * c;
        float v0 = xr[cc], v1 = xr[cc + 1], v2 = xr[cc + 8], v3 = xr[cc + 9];
        __half h0 = __float2half_rn(v0), h1 = __float2half_rn(v1);
        __half h2 = __float2half_rn(v2), h3 = __float2half_rn(v3);
        __half m0 = __float2half_rn(v0 - __half2float(h0));
        __half m1 = __float2half_rn(v1 - __half2float(h1));
        __half m2 = __float2half_rn(v2 - __half2float(h2));
        __half m3 = __float2half_rn(v3 - __half2float(h3));
        uint4 f; __half2 p;
        p = __halves2half2(h0, h1); f.x = *(uint32_t*)&p;
        p = __halves2half2(h2, h3); f.y = *(uint32_t*)&p;
        p = __halves2half2(m0, m1); f.z = *(uint32_t*)&p;
        p = __halves2half2(m2, m3); f.w = *(uint32_t*)&p;
        g_bf[(size_t)T * 32 + r * 4 + c] = f;
    }
}

// ============================================================
// Kernel 3b: tile + chunk key bounds from sorted keys (one block)
// ============================================================
__global__ void bounds_kernel() {
    int t = threadIdx.x;   // 1024
    #pragma unroll
    for (int u = t; u < NTILES; u += 1024) {
        const float* k = g_pkey + (size_t)u * 8;
        float lo = k[0], hi = k[0];
        #pragma unroll
        for (int r = 1; r < 8; ++r) { lo = fminf(lo, k[r]); hi = fmaxf(hi, k[r]); }
        g_tlo[u] = lo; g_thi[u] = hi;
    }
    __syncthreads();
    if (t < NCHUNK) {
        float lo = FLT_MAX, hi = -FLT_MAX;
        #pragma unroll
        for (int r = 0; r < NTILE; ++r) {
            lo = fminf(lo, g_tlo[t * NTILE + r]);
            hi = fmaxf(hi, g_thi[t * NTILE + r]);
        }
        g_clo[t] = lo; g_chi[t] = hi;
    }
}

// ============================================================
// Kernel 4: zigzag-pruned KNN + in-CTA merge (R14 config: 64 q/CTA)
// ============================================================
__global__ void __launch_bounds__(256) knn_zig_kernel()
{
    __shared__ uint4 sBf[2][NTILE * 32];   // 2 x 8KB
    __shared__ float ssq[2][CHUNK];
    __shared__ int   sjd[2][CHUNK];
    __shared__ ull   smerge[QCTA * NLIST * KNN];   // 32KB

    const int t    = threadIdx.x;
    const int lane = t & 31;
    const int w    = t >> 5;
    const int qg   = w & 3;
    const int jh   = w >> 2;            // tile-half 0/1
    const int gid  = lane >> 2;
    const int t4   = lane & 3;
    const int b    = blockIdx.x;
    const int p0   = b * QCTA + qg * 16 + gid;   // sorted query rows
    const int p1   = p0 + 8;

    uint32_t ah[4], am[4];
    {
        const __half* A0h = g_ah + (size_t)p0 * 16;
        const __half* A1h = g_ah + (size_t)p1 * 16;
        const __half* A0m = g_am + (size_t)p0 * 16;
        const __half* A1m = g_am + (size_t)p1 * 16;
        ah[0] = *(const uint32_t*)&A0h[2 * t4];
        ah[1] = *(const uint32_t*)&A1h[2 * t4];
        ah[2] = *(const uint32_t*)&A0h[2 * t4 + 8];
        ah[3] = *(const uint32_t*)&A1h[2 * t4 + 8];
        am[0] = *(const uint32_t*)&A0m[2 * t4];
        am[1] = *(const uint32_t*)&A1m[2 * t4];
        am[2] = *(const uint32_t*)&A0m[2 * t4 + 8];
        am[3] = *(const uint32_t*)&A1m[2 * t4 + 8];
    }
    const float qk0 = g_pkey[p0], qk1 = g_pkey[p1];
    const float sq0 = g_psq[p0],  sq1 = g_psq[p1];

    float td0[KNN], td1[KNN];
    int   ti0[KNN], ti1[KNN];
    #pragma unroll
    for (int k = 0; k < KNN; ++k) {
        td0[k] = FLT_MAX; ti0[k] = 0x7fffffff;
        td1[k] = FLT_MAX; ti1[k] = 0x7fffffff;
    }

    uint32_t sB_addr[2], sq_addr[2], sj_addr[2];
    #pragma unroll
    for (int u = 0; u < 2; ++u) {
        sB_addr[u] = smem_u32(&sBf[u][0]);
        sq_addr[u] = smem_u32(&ssq[u][0]);
        sj_addr[u] = smem_u32(&sjd[u][0]);
    }

    auto stage = [&](int bf, int c) {
        const uint4* src = g_bf + (size_t)c * (NTILE * 32);
        cp_async16(sB_addr[bf] + (uint32_t)t * 16, src + t);
        cp_async16(sB_addr[bf] + (uint32_t)(t + 256) * 16, src + t + 256);
        if (t < 32) {
            cp_async16(sq_addr[bf] + (uint32_t)t * 16, (const float4*)(g_psq + c * CHUNK) + t);
            cp_async16(sj_addr[bf] + (uint32_t)t * 16, (const int4*)(g_pidx + c * CHUNK) + t);
        }
        CP_COMMIT();
    };

    const int h0 = b >> 1;
    int nxtR = h0 + 1, nxtL = h0 - 1;
    int aliveR = 1, aliveL = 1, tog = 0;
    int cur = h0, bufA = 0;

    stage(0, h0);
    CP_WAIT0();
    __syncthreads();

    while (cur >= 0) {
        int pred = -1;
        {
            int aR = aliveR && (nxtR < NCHUNK);
            int aL = aliveL && (nxtL >= 0);
            if (aR && aL) pred = (tog == 0) ? nxtR : nxtL;
            else if (aR)  pred = nxtR;
            else if (aL)  pred = nxtL;
        }
        if (pred >= 0) stage(bufA ^ 1, pred);

        #pragma unroll
        for (int nt = 0; nt < 8; ++nt) {
            const int tl = jh * 8 + nt;
            const int gt = cur * NTILE + tl;

            float tlo = g_tlo[gt], thi = g_thi[gt];
            float gp0 = fmaxf(fmaxf(tlo - qk0, qk0 - thi), 0.0f);
            float gp1 = fmaxf(fmaxf(tlo - qk1, qk1 - thi), 0.0f);
            int nd = (gp0 * gp0 <= td0[KNN - 1] + sq0 + EPSA) ||
                     (gp1 * gp1 <= td1[KNN - 1] + sq1 + EPSA);
            if (!__any_sync(0xffffffffu, nd)) continue;

            uint4 f = sBf[bufA][tl * 32 + lane];
            const int jl = tl * 8 + 2 * t4;
            float2 s2 = *(const float2*)&ssq[bufA][jl];
            float c0 = s2.x, c1 = s2.y, c2 = s2.x, c3 = s2.y;
            mma_f16(c0, c1, c2, c3, ah[0], ah[1], ah[2], ah[3], f.x, f.y);
            mma_f16(c0, c1, c2, c3, ah[0], ah[1], ah[2], ah[3], f.z, f.w);
            mma_f16(c0, c1, c2, c3, am[0], am[1], am[2], am[3], f.x, f.y);
            if (fminf(c0, c1) < td0[KNN - 1]) {
                ins8(td0, ti0, c0, sjd[bufA][jl]); ins8(td0, ti0, c1, sjd[bufA][jl + 1]);
            }
            if (fminf(c2, c3) < td1[KNN - 1]) {
                ins8(td1, ti1, c2, sjd[bufA][jl]); ins8(td1, ti1, c3, sjd[bufA][jl + 1]);
            }
        }

        cur = -1;
        while (aliveR || aliveL) {
            int dir;
            if (aliveR && aliveL) { dir = tog; tog ^= 1; }
            else dir = aliveR ? 0 : 1;
            int c = (dir == 0) ? nxtR : nxtL;
            if (c < 0 || c >= NCHUNK) {
                if (dir == 0) aliveR = 0; else aliveL = 0;
                continue;
            }
            float bnd = (dir == 0) ? g_clo[c] : g_chi[c];
            float gp0 = (dir == 0) ? bnd - qk0 : qk0 - bnd;
            float gp1 = (dir == 0) ? bnd - qk1 : qk1 - bnd;
            gp0 = fmaxf(gp0 - SLACK, 0.0f);
            gp1 = fmaxf(gp1 - SLACK, 0.0f);
            float th0 = td0[KNN - 1] + sq0 + EPSA;
            float th1 = td1[KNN - 1] + sq1 + EPSA;
            int nd = (gp0 * gp0 <= th0) || (gp1 * gp1 <= th1);
            if (__syncthreads_or(nd)) {
                cur = c;
                if (dir == 0) nxtR++; else nxtL--;
                break;
            } else {
                if (dir == 0) aliveR = 0; else aliveL = 0;
            }
        }

        if (cur >= 0) {
            CP_WAIT0();
            __syncthreads();
            if (cur != pred) {
                stage(bufA ^ 1, cur);
                CP_WAIT0();
                __syncthreads();
            }
            bufA ^= 1;
        }
    }
    CP_WAIT0();

    // ---- in-CTA merge ----
    {
        const int li = jh * 4 + t4;
        const int q0l = qg * 16 + gid;
        const int q1l = q0l + 8;
        #pragma unroll
        for (int k = 0; k < KNN; ++k) {
            smerge[(q0l * NLIST + li) * KNN + k] = ((ull)fkey(td0[k]) << 32) | (uint32_t)ti0[k];
            smerge[(q1l * NLIST + li) * KNN + k] = ((ull)fkey(td1[k]) << 32) | (uint32_t)ti1[k];
        }
    }
    __syncthreads();

    #pragma unroll
    for (int pass = 0; pass < 2; ++pass) {
        int u  = pass * 256 + t;
        int q  = u >> 3;
        int l  = u & 7;
        ull v[KNN];
        #pragma unroll
        for (int k = 0; k < KNN; ++k)
            v[k] = smerge[(q * NLIST + l) * KNN + k];
        int oi = g_pidx[b * QCTA + q];
        #pragma unroll
        for (int k = 0; k < KNN; ++k) {
            ull m = v[0];
            #pragma unroll
            for (int x = 1; x < KNN; ++x) m = (v[x] < m) ? v[x] : m;
            #pragma unroll
            for (int off = 1; off < 8; off <<= 1) {
                ull o = __shfl_xor_sync(0xffffffffu, m, off, 8);
                m = (o < m) ? o : m;
            }
            if (l == 0)
                g_idx[oi * KNN + k] = (int)(uint32_t)(m & 0xffffffffull);
            #pragma unroll
            for (int x = 0; x < KNN; ++x)
                if (v[x] == m) v[x] = ~0ull;
        }
    }
}

// ============================================================
// Kernel 5: fused edge messages + mean + out MLP + concat
//   512 threads = 32 points x 16 channels per block
// ============================================================
#define FPTS 32

__global__ void __launch_bounds__(512)
feats_out_kernel(const float* __restrict__ xp,
                 const float* __restrict__ We,  const float* __restrict__ be,
                 const float* __restrict__ Wf1, const float* __restrict__ bf1,
                 const float* __restrict__ Wf2, const float* __restrict__ bf2,
                 float* __restrict__ out)
{
    __shared__ float sWd[16 * 16];
    __shared__ float sWb[16 * 16];
    __shared__ float sbe[16];
    __shared__ float sWf1[16 * 32], sbf1[32];
    __shared__ float sWf2[32 * 16], sbf2[16];
    __shared__ float sxi[FPTS * 16];
    __shared__ int   sj[FPTS * KNN];
    __shared__ float sxj[FPTS * KNN * 16];   // 16KB
    __shared__ float sfe[FPTS * 16];
    __shared__ float sf1[FPTS * 32];

    const int t  = threadIdx.x;
    const int i0 = blockIdx.x * FPTS;

    if (t < 256) {
        float top = We[t];
        float bot = We[256 + t];
        sWd[t] = top - bot;
        sWb[t] = bot;
    }
    if (t < 16) sbe[t] = be[t];
    if (t < 16 * 32) sWf1[t] = Wf1[t];
    if (t < 32) sbf1[t] = bf1[t];
    if (t < 32 * 16) sWf2[t] = Wf2[t];
    if (t < 16) sbf2[t] = bf2[t];
    sxi[t] = g_x[i0 * 16 + t];
    if (t < FPTS * KNN) sj[t] = g_idx[i0 * KNN + t];
    __syncthreads();

    {
        const float4* gx4 = (const float4*)g_x;
        float4* sxj4 = (float4*)sxj;
        #pragma unroll
        for (int u = t; u < FPTS * KNN * 4; u += 512) {
            int row = u >> 2, seg = u & 3;
            sxj4[u] = gx4[sj[row] * 4 + seg];
        }
    }
    __syncthreads();

    const int p = t >> 4;      // point 0..31
    const int h = t & 15;      // channel
    const int i = i0 + p;

    float pre = sbe[h];
    #pragma unroll
    for (int d = 0; d < 16; ++d) pre = fmaf(sxi[p * 16 + d], sWd[d * 16 + h], pre);

    float fsum = 0.0f;
    #pragma unroll
    for (int k = 0; k < KNN; ++k) {
        const float* xj = sxj + (p * KNN + k) * 16;
        float m = pre;
        #pragma unroll
        for (int d = 0; d < 16; ++d) m = fmaf(xj[d], sWb[d * 16 + h], m);
        fsum += silu_fast(m);
    }
    sfe[p * 16 + h] = fsum * 0.125f;
    __syncthreads();

    {
        float a0 = sbf1[h], a1 = sbf1[h + 16];
        #pragma unroll
        for (int d = 0; d < 16; ++d) {
            float fe = sfe[p * 16 + d];
            a0 = fmaf(fe, sWf1[d * 32 + h], a0);
            a1 = fmaf(fe, sWf1[d * 32 + h + 16], a1);
        }
        sf1[p * 32 + h]      = silu_fast(a0);
        sf1[p * 32 + h + 16] = silu_fast(a1);
    }
    __syncthreads();

    {
        float a = sbf2[h];
        #pragma unroll
        for (int d = 0; d < 32; ++d) a = fmaf(sf1[p * 32 + d], sWf2[d * 16 + h], a);
        out[i * (16 + DIN) + h] = a;
    }
    if (h < DIN)
        out[i * (16 + DIN) + 16 + h] = xp[i * DIN + h];
}

// ============================================================
extern "C" void kernel_launch(void* const* d_in, const int* in_sizes, int n_in,
                              void* d_out, int out_size)
{
    const float* xp  = (const float*)d_in[0];
    const float* W1  = (const float*)d_in[1];
    const float* b1  = (const float*)d_in[2];
    const float* W2  = (const float*)d_in[3];
    const float* b2  = (const float*)d_in[4];
    const float* W3  = (const float*)d_in[5];
    const float* b3  = (const float*)d_in[6];
    const float* We  = (const float*)d_in[7];
    const float* be  = (const float*)d_in[8];
    const float* Wf1 = (const float*)d_in[9];
    const float* bf1 = (const float*)d_in[10];
    const float* Wf2 = (const float*)d_in[11];
    const float* bf2 = (const float*)d_in[12];
    float* out = (float*)d_out;

    zeroh_kernel<<<1, NBIN>>>();
    mlp_kernel<<<N / 256, 256>>>(xp, W1, b1, W2, b2, W3, b3);
    scan_kernel<<<1, 32>>>();
    scatter_kernel<<<N / 256, 256>>>();
    bounds_kernel<<<1, 1024>>>();
    knn_zig_kernel<<<N / QCTA, 256>>>();
    feats_out_kernel<<<N / FPTS, 512>>>(xp, We, be, Wf1, bf1, Wf2, bf2, out);
}

// round 17
// speedup vs baseline: 1.4166x; 1.0169x over previous
#include <cuda_runtime.h>
#include <cuda_fp16.h>
#include <math.h>
#include <float.h>
#include <stdint.h>

#define N       16384
#define DIN     13
#define KNN     8
#define NBIN    1024
#define QCTA    64               // sorted queries per CTA
#define CHUNK   128              // j per chunk
#define NCHUNK  (N / CHUNK)      // 128
#define NTILE   (CHUNK / 8)      // 16 tiles per chunk
#define NTILES  (N / 8)          // 2048 global tiles
#define NLIST   8                // 4 t4-slices x 2 tile-halves
#define EPSA    1e-3f            // abs margin on d2 threshold (MMA approx)
#define SLACK   0.011f           // key slack (>= bucket bin width 10/1024)

typedef unsigned long long ull;

// ---- scratch (no allocs allowed) ----
__device__ float  g_x[N * 16];            // embedded points (original order)
__device__ float  g_sq[N];
__device__ float  g_key[N];
__device__ int    g_hist[NBIN];
__device__ int    g_off[NBIN];
__device__ int    g_pos[N];               // point -> sorted position
__device__ float  g_pkey[N];              // sorted keys
__device__ float  g_psq[N];               // sorted sq
__device__ int    g_pidx[N];              // sorted pos -> original index
__device__ __half g_ah[N * 16];           // sorted fp16 hi of -2x
__device__ __half g_am[N * 16];           // sorted fp16 mid of -2x
__device__ uint4  g_bf[NCHUNK * NTILE * 32]; // sorted B fragments
__device__ float  g_clo[NCHUNK], g_chi[NCHUNK];
__device__ float  g_tlo[NTILES], g_thi[NTILES];
__device__ int    g_idx[N * KNN];         // final knn (original indices)

__device__ __forceinline__ float silu_f(float v) { return v / (1.0f + expf(-v)); }
__device__ __forceinline__ float silu_fast(float v) { return __fdividef(v, 1.0f + __expf(-v)); }
__device__ __forceinline__ int keybin(float k) {
    int b = (int)((k + 5.0f) * (NBIN / 10.0f));
    return b < 0 ? 0 : (b > NBIN - 1 ? NBIN - 1 : b);
}
__device__ __forceinline__ uint32_t smem_u32(const void* p) {
    uint32_t a;
    asm("{ .reg .u64 t; cvta.to.shared.u64 t, %1; cvt.u32.u64 %0, t; }"
        : "=r"(a) : "l"(p));
    return a;
}
__device__ __forceinline__ void cp_async16(uint32_t saddr, const void* g) {
    asm volatile("cp.async.cg.shared.global [%0], [%1], 16;" :: "r"(saddr), "l"(g));
}
#define CP_COMMIT() asm volatile("cp.async.commit_group;" ::: "memory")
#define CP_WAIT0()  asm volatile("cp.async.wait_group 0;" ::: "memory")

// sortable uint from float (ascending uint == ascending float, any sign)
__device__ __forceinline__ uint32_t fkey(float f) {
    uint32_t u = __float_as_uint(f);
    return u ^ ((u >> 31) ? 0xFFFFFFFFu : 0x80000000u);
}

// m16n8k16 fp16 mma, fp32 accumulate (PTX sm_80+, valid under compute_103)
__device__ __forceinline__ void mma_f16(float& c0, float& c1, float& c2, float& c3,
                                        uint32_t a0, uint32_t a1, uint32_t a2, uint32_t a3,
                                        uint32_t b0, uint32_t b1) {
    asm volatile(
        "mma.sync.aligned.m16n8k16.row.col.f32.f16.f16.f32 "
        "{%0,%1,%2,%3}, {%4,%5,%6,%7}, {%8,%9}, {%0,%1,%2,%3};"
        : "+f"(c0), "+f"(c1), "+f"(c2), "+f"(c3)
        : "r"(a0), "r"(a1), "r"(a2), "r"(a3), "r"(b0), "r"(b1));
}

__device__ __forceinline__ void ins8(float* td, int* ti, float d, int j) {
    if (d < td[KNN - 1]) {
        td[KNN - 1] = d; ti[KNN - 1] = j;
        #pragma unroll
        for (int s = KNN - 1; s >= 1; --s) {
            if (td[s] < td[s - 1] || (td[s] == td[s - 1] && ti[s] < ti[s - 1])) {
                float tf = td[s]; td[s] = td[s-1]; td[s-1] = tf;
                int   tn = ti[s]; ti[s] = ti[s-1]; ti[s-1] = tn;
            }
        }
    }
}

// ============================================================
// Kernel 0: zero histogram
// ============================================================
__global__ void zeroh_kernel() { g_hist[threadIdx.x] = 0; }

// ============================================================
// Kernel 1: per-point MLP -> x, sq, key + histogram (fused)
// ============================================================
__global__ void mlp_kernel(const float* __restrict__ xp,
                           const float* __restrict__ W1, const float* __restrict__ b1,
                           const float* __restrict__ W2, const float* __restrict__ b2,
                           const float* __restrict__ W3, const float* __restrict__ b3)
{
    __shared__ float sW1[DIN * 8], sb1[8];
    __shared__ float sW2[8 * 16],  sb2[16];
    __shared__ float sW3[16 * 15], sb3[15];

    int t = threadIdx.x;
    for (int i = t; i < DIN * 8; i += blockDim.x) sW1[i] = W1[i];
    for (int i = t; i < 8;       i += blockDim.x) sb1[i] = b1[i];
    for (int i = t; i < 8 * 16;  i += blockDim.x) sW2[i] = W2[i];
    for (int i = t; i < 16;      i += blockDim.x) sb2[i] = b2[i];
    for (int i = t; i < 16 * 15; i += blockDim.x) sW3[i] = W3[i];
    for (int i = t; i < 15;      i += blockDim.x) sb3[i] = b3[i];
    __syncthreads();

    int i = blockIdx.x * blockDim.x + t;
    if (i >= N) return;

    float in[DIN];
    #pragma unroll
    for (int d = 0; d < DIN; ++d) in[d] = xp[i * DIN + d];

    float h1[8];
    #pragma unroll
    for (int h = 0; h < 8; ++h) {
        float a = sb1[h];
        #pragma unroll
        for (int d = 0; d < DIN; ++d) a = fmaf(in[d], sW1[d * 8 + h], a);
        h1[h] = silu_f(a);
    }
    float h2[16];
    #pragma unroll
    for (int h = 0; h < 16; ++h) {
        float a = sb2[h];
        #pragma unroll
        for (int d = 0; d < 8; ++d) a = fmaf(h1[d], sW2[d * 16 + h], a);
        h2[h] = silu_f(a);
    }
    float xr[16];
    #pragma unroll
    for (int h = 0; h < 15; ++h) {
        float a = sb3[h];
        #pragma unroll
        for (int d = 0; d < 16; ++d) a = fmaf(h2[d], sW3[d * 15 + h], a);
        xr[h] = a;
    }
    xr[15] = in[DIN - 1];

    float s = 0.0f;
    #pragma unroll
    for (int k = 0; k < 16; ++k) s = fmaf(xr[k], xr[k], s);

    #pragma unroll
    for (int k = 0; k < 16; ++k) g_x[i * 16 + k] = xr[k];
    g_sq[i]  = s;
    g_key[i] = xr[15];
    atomicAdd(&g_hist[keybin(xr[15])], 1);
}

// ============================================================
// Kernel 2: single-warp exclusive scan of 1024 bins
// ============================================================
__global__ void scan_kernel() {
    int lane = threadIdx.x;     // 32 threads
    int base = lane * 32;
    int vals[32];
    int sum = 0;
    #pragma unroll
    for (int i = 0; i < 32; ++i) { vals[i] = g_hist[base + i]; sum += vals[i]; }
    int inc = sum;
    #pragma unroll
    for (int d = 1; d < 32; d <<= 1) {
        int o = __shfl_up_sync(0xffffffffu, inc, d);
        if (lane >= d) inc += o;
    }
    int run = inc - sum;   // exclusive offset of this lane's block
    #pragma unroll
    for (int i = 0; i < 32; ++i) { g_off[base + i] = run; run += vals[i]; }
}

// ============================================================
// Kernel 3a: positions only (short atomic chain)
// ============================================================
__global__ void pos_kernel() {
    int i = blockIdx.x * blockDim.x + threadIdx.x;
    g_pos[i] = atomicAdd(&g_off[keybin(g_key[i])], 1);
}

// ============================================================
// Kernel 3b: payload — thread = (point, quarter)
//   quarter c handles dims {2c, 2c+1, 2c+8, 2c+9}
// ============================================================
__global__ void payload_kernel() {
    int u = blockIdx.x * blockDim.x + threadIdx.x;   // 0..4N-1
    int i = u >> 2;
    int c = u & 3;
    int pos = g_pos[i];

    float2 vlo = *(const float2*)&g_x[i * 16 + 2 * c];       // dims 2c, 2c+1
    float2 vhi = *(const float2*)&g_x[i * 16 + 2 * c + 8];   // dims 2c+8, 2c+9

    if (c == 0) {
        g_pkey[pos] = g_key[i];
        g_psq[pos]  = g_sq[i];
        g_pidx[pos] = i;
    }

    // A splits: -2x (hi, mid)
    {
        float a0 = -2.0f * vlo.x, a1 = -2.0f * vlo.y;
        float a2 = -2.0f * vhi.x, a3 = -2.0f * vhi.y;
        __half h0 = __float2half_rn(a0), h1 = __float2half_rn(a1);
        __half h2 = __float2half_rn(a2), h3 = __float2half_rn(a3);
        __half m0 = __float2half_rn(a0 - __half2float(h0));
        __half m1 = __float2half_rn(a1 - __half2float(h1));
        __half m2 = __float2half_rn(a2 - __half2float(h2));
        __half m3 = __float2half_rn(a3 - __half2float(h3));
        __half2 p;
        p = __halves2half2(h0, h1); *(uint32_t*)&g_ah[(size_t)pos * 16 + 2 * c]     = *(uint32_t*)&p;
        p = __halves2half2(h2, h3); *(uint32_t*)&g_ah[(size_t)pos * 16 + 2 * c + 8] = *(uint32_t*)&p;
        p = __halves2half2(m0, m1); *(uint32_t*)&g_am[(size_t)pos * 16 + 2 * c]     = *(uint32_t*)&p;
        p = __halves2half2(m2, m3); *(uint32_t*)&g_am[(size_t)pos * 16 + 2 * c + 8] = *(uint32_t*)&p;
    }

    // B fragment: x (hi, mid)
    {
        __half h0 = __float2half_rn(vlo.x), h1 = __float2half_rn(vlo.y);
        __half h2 = __float2half_rn(vhi.x), h3 = __float2half_rn(vhi.y);
        __half m0 = __float2half_rn(vlo.x - __half2float(h0));
        __half m1 = __float2half_rn(vlo.y - __half2float(h1));
        __half m2 = __float2half_rn(vhi.x - __half2float(h2));
        __half m3 = __float2half_rn(vhi.y - __half2float(h3));
        uint4 f; __half2 p;
        p = __halves2half2(h0, h1); f.x = *(uint32_t*)&p;
        p = __halves2half2(h2, h3); f.y = *(uint32_t*)&p;
        p = __halves2half2(m0, m1); f.z = *(uint32_t*)&p;
        p = __halves2half2(m2, m3); f.w = *(uint32_t*)&p;
        int T = pos >> 3, r = pos & 7;
        g_bf[(size_t)T * 32 + r * 4 + c] = f;
    }
}

// ============================================================
// Kernel 3c: tile + chunk key bounds from sorted keys (one block)
// ============================================================
__global__ void bounds_kernel() {
    int t = threadIdx.x;   // 1024
    #pragma unroll
    for (int u = t; u < NTILES; u += 1024) {
        const float* k = g_pkey + (size_t)u * 8;
        float lo = k[0], hi = k[0];
        #pragma unroll
        for (int r = 1; r < 8; ++r) { lo = fminf(lo, k[r]); hi = fmaxf(hi, k[r]); }
        g_tlo[u] = lo; g_thi[u] = hi;
    }
    __syncthreads();
    if (t < NCHUNK) {
        float lo = FLT_MAX, hi = -FLT_MAX;
        #pragma unroll
        for (int r = 0; r < NTILE; ++r) {
            lo = fminf(lo, g_tlo[t * NTILE + r]);
            hi = fmaxf(hi, g_thi[t * NTILE + r]);
        }
        g_clo[t] = lo; g_chi[t] = hi;
    }
}

// ============================================================
// Kernel 4: zigzag-pruned KNN + in-CTA merge (64 q/CTA)
// ============================================================
__global__ void __launch_bounds__(256) knn_zig_kernel()
{
    __shared__ uint4 sBf[2][NTILE * 32];   // 2 x 8KB
    __shared__ float ssq[2][CHUNK];
    __shared__ int   sjd[2][CHUNK];
    __shared__ ull   smerge[QCTA * NLIST * KNN];   // 32KB

    const int t    = threadIdx.x;
    const int lane = t & 31;
    const int w    = t >> 5;
    const int qg   = w & 3;
    const int jh   = w >> 2;            // tile-half 0/1
    const int gid  = lane >> 2;
    const int t4   = lane & 3;
    const int b    = blockIdx.x;
    const int p0   = b * QCTA + qg * 16 + gid;   // sorted query rows
    const int p1   = p0 + 8;

    uint32_t ah[4], am[4];
    {
        const __half* A0h = g_ah + (size_t)p0 * 16;
        const __half* A1h = g_ah + (size_t)p1 * 16;
        const __half* A0m = g_am + (size_t)p0 * 16;
        const __half* A1m = g_am + (size_t)p1 * 16;
        ah[0] = *(const uint32_t*)&A0h[2 * t4];
        ah[1] = *(const uint32_t*)&A1h[2 * t4];
        ah[2] = *(const uint32_t*)&A0h[2 * t4 + 8];
        ah[3] = *(const uint32_t*)&A1h[2 * t4 + 8];
        am[0] = *(const uint32_t*)&A0m[2 * t4];
        am[1] = *(const uint32_t*)&A1m[2 * t4];
        am[2] = *(const uint32_t*)&A0m[2 * t4 + 8];
        am[3] = *(const uint32_t*)&A1m[2 * t4 + 8];
    }
    const float qk0 = g_pkey[p0], qk1 = g_pkey[p1];
    const float sq0 = g_psq[p0],  sq1 = g_psq[p1];

    float td0[KNN], td1[KNN];
    int   ti0[KNN], ti1[KNN];
    #pragma unroll
    for (int k = 0; k < KNN; ++k) {
        td0[k] = FLT_MAX; ti0[k] = 0x7fffffff;
        td1[k] = FLT_MAX; ti1[k] = 0x7fffffff;
    }

    uint32_t sB_addr[2], sq_addr[2], sj_addr[2];
    #pragma unroll
    for (int u = 0; u < 2; ++u) {
        sB_addr[u] = smem_u32(&sBf[u][0]);
        sq_addr[u] = smem_u32(&ssq[u][0]);
        sj_addr[u] = smem_u32(&sjd[u][0]);
    }

    auto stage = [&](int bf, int c) {
        const uint4* src = g_bf + (size_t)c * (NTILE * 32);
        cp_async16(sB_addr[bf] + (uint32_t)t * 16, src + t);
        cp_async16(sB_addr[bf] + (uint32_t)(t + 256) * 16, src + t + 256);
        if (t < 32) {
            cp_async16(sq_addr[bf] + (uint32_t)t * 16, (const float4*)(g_psq + c * CHUNK) + t);
            cp_async16(sj_addr[bf] + (uint32_t)t * 16, (const int4*)(g_pidx + c * CHUNK) + t);
        }
        CP_COMMIT();
    };

    const int h0 = b >> 1;
    int nxtR = h0 + 1, nxtL = h0 - 1;
    int aliveR = 1, aliveL = 1, tog = 0;
    int cur = h0, bufA = 0;

    stage(0, h0);
    CP_WAIT0();
    __syncthreads();

    while (cur >= 0) {
        int pred = -1;
        {
            int aR = aliveR && (nxtR < NCHUNK);
            int aL = aliveL && (nxtL >= 0);
            if (aR && aL) pred = (tog == 0) ? nxtR : nxtL;
            else if (aR)  pred = nxtR;
            else if (aL)  pred = nxtL;
        }
        if (pred >= 0) stage(bufA ^ 1, pred);

        #pragma unroll
        for (int nt = 0; nt < 8; ++nt) {
            const int tl = jh * 8 + nt;
            const int gt = cur * NTILE + tl;

            float tlo = g_tlo[gt], thi = g_thi[gt];
            float gp0 = fmaxf(fmaxf(tlo - qk0, qk0 - thi), 0.0f);
            float gp1 = fmaxf(fmaxf(tlo - qk1, qk1 - thi), 0.0f);
            int nd = (gp0 * gp0 <= td0[KNN - 1] + sq0 + EPSA) ||
                     (gp1 * gp1 <= td1[KNN - 1] + sq1 + EPSA);
            if (!__any_sync(0xffffffffu, nd)) continue;

            uint4 f = sBf[bufA][tl * 32 + lane];
            const int jl = tl * 8 + 2 * t4;
            float2 s2 = *(const float2*)&ssq[bufA][jl];
            float c0 = s2.x, c1 = s2.y, c2 = s2.x, c3 = s2.y;
            mma_f16(c0, c1, c2, c3, ah[0], ah[1], ah[2], ah[3], f.x, f.y);
            mma_f16(c0, c1, c2, c3, ah[0], ah[1], ah[2], ah[3], f.z, f.w);
            mma_f16(c0, c1, c2, c3, am[0], am[1], am[2], am[3], f.x, f.y);
            if (fminf(c0, c1) < td0[KNN - 1]) {
                ins8(td0, ti0, c0, sjd[bufA][jl]); ins8(td0, ti0, c1, sjd[bufA][jl + 1]);
            }
            if (fminf(c2, c3) < td1[KNN - 1]) {
                ins8(td1, ti1, c2, sjd[bufA][jl]); ins8(td1, ti1, c3, sjd[bufA][jl + 1]);
            }
        }

        cur = -1;
        while (aliveR || aliveL) {
            int dir;
            if (aliveR && aliveL) { dir = tog; tog ^= 1; }
            else dir = aliveR ? 0 : 1;
            int c = (dir == 0) ? nxtR : nxtL;
            if (c < 0 || c >= NCHUNK) {
                if (dir == 0) aliveR = 0; else aliveL = 0;
                continue;
            }
            float bnd = (dir == 0) ? g_clo[c] : g_chi[c];
            float gp0 = (dir == 0) ? bnd - qk0 : qk0 - bnd;
            float gp1 = (dir == 0) ? bnd - qk1 : qk1 - bnd;
            gp0 = fmaxf(gp0 - SLACK, 0.0f);
            gp1 = fmaxf(gp1 - SLACK, 0.0f);
            float th0 = td0[KNN - 1] + sq0 + EPSA;
            float th1 = td1[KNN - 1] + sq1 + EPSA;
            int nd = (gp0 * gp0 <= th0) || (gp1 * gp1 <= th1);
            if (__syncthreads_or(nd)) {
                cur = c;
                if (dir == 0) nxtR++; else nxtL--;
                break;
            } else {
                if (dir == 0) aliveR = 0; else aliveL = 0;
            }
        }

        if (cur >= 0) {
            CP_WAIT0();
            __syncthreads();
            if (cur != pred) {
                stage(bufA ^ 1, cur);
                CP_WAIT0();
                __syncthreads();
            }
            bufA ^= 1;
        }
    }
    CP_WAIT0();

    // ---- in-CTA merge ----
    {
        const int li = jh * 4 + t4;
        const int q0l = qg * 16 + gid;
        const int q1l = q0l + 8;
        #pragma unroll
        for (int k = 0; k < KNN; ++k) {
            smerge[(q0l * NLIST + li) * KNN + k] = ((ull)fkey(td0[k]) << 32) | (uint32_t)ti0[k];
            smerge[(q1l * NLIST + li) * KNN + k] = ((ull)fkey(td1[k]) << 32) | (uint32_t)ti1[k];
        }
    }
    __syncthreads();

    #pragma unroll
    for (int pass = 0; pass < 2; ++pass) {
        int u  = pass * 256 + t;
        int q  = u >> 3;
        int l  = u & 7;
        ull v[KNN];
        #pragma unroll
        for (int k = 0; k < KNN; ++k)
            v[k] = smerge[(q * NLIST + l) * KNN + k];
        int oi = g_pidx[b * QCTA + q];
        #pragma unroll
        for (int k = 0; k < KNN; ++k) {
            ull m = v[0];
            #pragma unroll
            for (int x = 1; x < KNN; ++x) m = (v[x] < m) ? v[x] : m;
            #pragma unroll
            for (int off = 1; off < 8; off <<= 1) {
                ull o = __shfl_xor_sync(0xffffffffu, m, off, 8);
                m = (o < m) ? o : m;
            }
            if (l == 0)
                g_idx[oi * KNN + k] = (int)(uint32_t)(m & 0xffffffffull);
            #pragma unroll
            for (int x = 0; x < KNN; ++x)
                if (v[x] == m) v[x] = ~0ull;
        }
    }
}

// ============================================================
// Kernel 5: fused edge messages + mean + out MLP + concat
// ============================================================
__global__ void __launch_bounds__(256)
feats_out_kernel(const float* __restrict__ xp,
                 const float* __restrict__ We,  const float* __restrict__ be,
                 const float* __restrict__ Wf1, const float* __restrict__ bf1,
                 const float* __restrict__ Wf2, const float* __restrict__ bf2,
                 float* __restrict__ out)
{
    __shared__ float sWd[16 * 16];
    __shared__ float sWb[16 * 16];
    __shared__ float sbe[16];
    __shared__ float sWf1[16 * 32], sbf1[32];
    __shared__ float sWf2[32 * 16], sbf2[16];
    __shared__ float sxi[16 * 16];
    __shared__ int   sj[16 * KNN];
    __shared__ float sxj[16 * KNN * 16];
    __shared__ float sfe[16 * 16];
    __shared__ float sf1[16 * 32];

    const int t  = threadIdx.x;
    const int i0 = blockIdx.x * 16;

    {
        float top = We[t];
        float bot = We[256 + t];
        sWd[t] = top - bot;
        sWb[t] = bot;
    }
    if (t < 16) sbe[t] = be[t];
    for (int u = t; u < 16 * 32; u += 256) sWf1[u] = Wf1[u];
    if (t < 32) sbf1[t] = bf1[t];
    for (int u = t; u < 32 * 16; u += 256) sWf2[u] = Wf2[u];
    if (t < 16) sbf2[t] = bf2[t];
    sxi[t] = g_x[i0 * 16 + t];
    if (t < 16 * KNN) sj[t] = g_idx[i0 * KNN + t];
    __syncthreads();

    {
        const float4* gx4 = (const float4*)g_x;
        float4* sxj4 = (float4*)sxj;
        #pragma unroll
        for (int u = t; u < 16 * KNN * 4; u += 256) {
            int row = u >> 2, seg = u & 3;
            sxj4[u] = gx4[sj[row] * 4 + seg];
        }
    }
    __syncthreads();

    const int p = t >> 4;
    const int h = t & 15;
    const int i = i0 + p;

    float pre = sbe[h];
    #pragma unroll
    for (int d = 0; d < 16; ++d) pre = fmaf(sxi[p * 16 + d], sWd[d * 16 + h], pre);

    float fsum = 0.0f;
    #pragma unroll
    for (int k = 0; k < KNN; ++k) {
        const float* xj = sxj + (p * KNN + k) * 16;
        float m = pre;
        #pragma unroll
        for (int d = 0; d < 16; ++d) m = fmaf(xj[d], sWb[d * 16 + h], m);
        fsum += silu_fast(m);
    }
    sfe[p * 16 + h] = fsum * 0.125f;
    __syncthreads();

    {
        float a0 = sbf1[h], a1 = sbf1[h + 16];
        #pragma unroll
        for (int d = 0; d < 16; ++d) {
            float fe = sfe[p * 16 + d];
            a0 = fmaf(fe, sWf1[d * 32 + h], a0);
            a1 = fmaf(fe, sWf1[d * 32 + h + 16], a1);
        }
        sf1[p * 32 + h]      = silu_fast(a0);
        sf1[p * 32 + h + 16] = silu_fast(a1);
    }
    __syncthreads();

    {
        float a = sbf2[h];
        #pragma unroll
        for (int d = 0; d < 32; ++d) a = fmaf(sf1[p * 32 + d], sWf2[d * 16 + h], a);
        out[i * (16 + DIN) + h] = a;
    }
    if (h < DIN)
        out[i * (16 + DIN) + 16 + h] = xp[i * DIN + h];
}

// ============================================================
extern "C" void kernel_launch(void* const* d_in, const int* in_sizes, int n_in,
                              void* d_out, int out_size)
{
    const float* xp  = (const float*)d_in[0];
    const float* W1  = (const float*)d_in[1];
    const float* b1  = (const float*)d_in[2];
    const float* W2  = (const float*)d_in[3];
    const float* b2  = (const float*)d_in[4];
    const float* W3  = (const float*)d_in[5];
    const float* b3  = (const float*)d_in[6];
    const float* We  = (const float*)d_in[7];
    const float* be  = (const float*)d_in[8];
    const float* Wf1 = (const float*)d_in[9];
    const float* bf1 = (const float*)d_in[10];
    const float* Wf2 = (const float*)d_in[11];
    const float* bf2 = (const float*)d_in[12];
    float* out = (float*)d_out;

    zeroh_kernel<<<1, NBIN>>>();
    mlp_kernel<<<N / 256, 256>>>(xp, W1, b1, W2, b2, W3, b3);
    scan_kernel<<<1, 32>>>();
    pos_kernel<<<N / 128, 128>>>();
    payload_kernel<<<(N * 4) / 256, 256>>>();
    bounds_kernel<<<1, 1024>>>();
    knn_zig_kernel<<<N / QCTA, 256>>>();
    feats_out_kernel<<<N / 16, 256>>>(xp, We, be, Wf1, bf1, Wf2, bf2, out);
}